// round 1
// baseline (speedup 1.0000x reference)
#include <cuda_runtime.h>
#include <math.h>

// ---------------- problem constants ----------------
#define NB    8          // batch
#define LL    250        // sequence length (T)
#define MR    2000       // NB*LL rows
#define DM    512        // d_model
#define DI    1024       // d_inner
#define DS    64         // d_state
#define DTR   32         // dt_rank
#define XDN   160        // dt_rank + 2*d_state
#define FLAT  120000     // fc1 input dim

// ---------------- scratch (static device globals; allocation-free) ----------------
__device__ float g_u[MR * DM];             // padded input u [2000,512]
__device__ float g_xz[MR * 2 * DI];        // in_proj output [2000,2048]
__device__ float g_xconv[MR * DI];         // conv+silu     [2000,1024]
__device__ float g_xdblp[8 * MR * XDN];    // x_proj split-K partials
__device__ float g_xdbl[MR * XDN];         // x_proj output [2000,160]
__device__ float g_dt[MR * DI];            // softplus(dt)  [2000,1024]
__device__ float g_yss[MR * DI];           // scan out * silu(z)
__device__ float g_outrawp[4 * MR * DM];   // out_proj split-K partials
__device__ float g_outraw[MR * DM];        // out_proj output [2000,512]
__device__ float g_act[NB * FLAT];         // permuted selu output [8,120000]
__device__ float g_y1p[8 * NB * 512];      // fc1 split-K partials
__device__ float g_y1[NB * 512];
__device__ float g_y2[NB * 256];
__device__ float g_y3[NB * 64];

// ---------------- math helpers ----------------
__device__ __forceinline__ float siluf(float v) { return v / (1.f + __expf(-v)); }
__device__ __forceinline__ float softplusf(float v) {
    return (v > 20.f) ? v : log1pf(__expf(v));
}
__device__ __forceinline__ float seluf(float v) {
    const float a = 1.6732632423543772f, s = 1.0507009873554805f;
    return v > 0.f ? s * v : s * a * (__expf(v) - 1.f);
}

// ---------------- kernels ----------------

// build u[2000,512] from x (reshape is identity up to row width; pad 480->512)
__global__ void pack_u(const float* __restrict__ x) {
    int i = blockIdx.x * blockDim.x + threadIdx.x;
    if (i >= MR * DM) return;
    int m = i >> 9, k = i & 511;
    g_u[i] = (k < 480) ? x[m * 480 + k] : 0.f;
}

// C[z][M,N] = A[M,K-slice] * B[N,K-slice]^T   (K split across gridDim.z, slice stored per z)
// block 256 threads, 128x128 tile, 8x8 per thread
__global__ void sgemm_nt(const float* __restrict__ A, const float* __restrict__ Bm,
                         float* __restrict__ C, int M, int N, int K) {
    const int BK = 8;
    __shared__ float As[BK][128];
    __shared__ float Bs[BK][128];
    int m0 = blockIdx.y * 128, n0 = blockIdx.x * 128;
    int kLen = K / gridDim.z;
    int k0 = blockIdx.z * kLen;
    int tid = threadIdx.x;
    int lr = tid >> 1;
    int lc = (tid & 1) << 2;
    int tx = tid & 15, ty = tid >> 4;

    float acc[8][8];
#pragma unroll
    for (int i = 0; i < 8; i++)
#pragma unroll
        for (int j = 0; j < 8; j++) acc[i][j] = 0.f;

    int aRow = m0 + lr, bRow = n0 + lr;
    bool aOk = aRow < M, bOk = bRow < N;
    const float* Ap = A + (size_t)(aOk ? aRow : 0) * K + lc;
    const float* Bp = Bm + (size_t)(bOk ? bRow : 0) * K + lc;

    for (int k = k0; k < k0 + kLen; k += BK) {
        float4 a4 = aOk ? *(const float4*)(Ap + k) : make_float4(0.f, 0.f, 0.f, 0.f);
        float4 b4 = bOk ? *(const float4*)(Bp + k) : make_float4(0.f, 0.f, 0.f, 0.f);
        As[lc + 0][lr] = a4.x; As[lc + 1][lr] = a4.y; As[lc + 2][lr] = a4.z; As[lc + 3][lr] = a4.w;
        Bs[lc + 0][lr] = b4.x; Bs[lc + 1][lr] = b4.y; Bs[lc + 2][lr] = b4.z; Bs[lc + 3][lr] = b4.w;
        __syncthreads();
#pragma unroll
        for (int kk = 0; kk < BK; kk++) {
            float4 a0 = *(const float4*)&As[kk][ty * 8];
            float4 a1 = *(const float4*)&As[kk][ty * 8 + 4];
            float4 b0 = *(const float4*)&Bs[kk][tx * 8];
            float4 b1 = *(const float4*)&Bs[kk][tx * 8 + 4];
            float ar[8] = {a0.x, a0.y, a0.z, a0.w, a1.x, a1.y, a1.z, a1.w};
            float br[8] = {b0.x, b0.y, b0.z, b0.w, b1.x, b1.y, b1.z, b1.w};
#pragma unroll
            for (int i = 0; i < 8; i++)
#pragma unroll
                for (int j = 0; j < 8; j++) acc[i][j] = fmaf(ar[i], br[j], acc[i][j]);
        }
        __syncthreads();
    }

    size_t zoff = (size_t)blockIdx.z * M * N;
#pragma unroll
    for (int i = 0; i < 8; i++) {
        int row = m0 + ty * 8 + i;
        if (row < M) {
            float* Cp = C + zoff + (size_t)row * N + n0 + tx * 8;
#pragma unroll
            for (int j = 0; j < 8; j++)
                if (n0 + tx * 8 + j < N) Cp[j] = acc[i][j];
        }
    }
}

// deterministic split-K reduction: dst[i] = sum_p src[p*n + i]
__global__ void reduce_parts(float* __restrict__ dst, const float* __restrict__ src,
                             int n, int parts) {
    int i = blockIdx.x * blockDim.x + threadIdx.x;
    if (i >= n) return;
    float s = 0.f;
    for (int p = 0; p < parts; p++) s += src[(size_t)p * n + i];
    dst[i] = s;
}

// depthwise causal conv (width 4) + silu over x-part of xz
__global__ void conv_silu(const float* __restrict__ cw, const float* __restrict__ cb) {
    int i = blockIdx.x * blockDim.x + threadIdx.x;
    if (i >= MR * DI) return;
    int m = i >> 10, d = i & (DI - 1);
    int t = m % LL;
    const float* xp = g_xz + (size_t)m * (2 * DI) + d;
    float v = cb[d] + cw[d * 4 + 3] * xp[0];
    if (t >= 1) v += cw[d * 4 + 2] * xp[-(2 * DI)];
    if (t >= 2) v += cw[d * 4 + 1] * xp[-(4 * DI)];
    if (t >= 3) v += cw[d * 4 + 0] * xp[-(6 * DI)];
    g_xconv[i] = siluf(v);
}

// dt = softplus(xdbl[:, :32] @ dt_proj_w^T + dt_proj_b)  grid (125,4), block 256
__global__ void dt_softplus(const float* __restrict__ W, const float* __restrict__ bias) {
    __shared__ float sw[32 * 256];   // sw[r*256 + j] = W[(d0+j)*32 + r]
    __shared__ float sin[16][32];
    int tid = threadIdx.x;
    int d0 = blockIdx.y * 256;
    int m0 = blockIdx.x * 16;
    for (int i = tid; i < 32 * 256; i += 256) {
        int j = i >> 5, r = i & 31;
        sw[r * 256 + j] = W[(d0 + j) * 32 + r];
    }
    for (int i = tid; i < 16 * 32; i += 256)
        sin[i >> 5][i & 31] = g_xdbl[(m0 + (i >> 5)) * XDN + (i & 31)];
    __syncthreads();
    int d = d0 + tid;
    float bv = bias[d];
#pragma unroll 4
    for (int mm = 0; mm < 16; mm++) {
        float s = bv;
#pragma unroll
        for (int r = 0; r < 32; r++) s = fmaf(sw[r * 256 + tid], sin[mm][r], s);
        g_dt[(m0 + mm) * DI + d] = softplusf(s);
    }
}

// selective scan: one warp per (b,d) channel, 2 states per lane, 250 sequential steps
__global__ void scan_kernel(const float* __restrict__ A_log, const float* __restrict__ Dp) {
    int warp = threadIdx.x >> 5, lane = threadIdx.x & 31;
    int blk = blockIdx.x;          // 1024 blocks
    int b = blk >> 7, dg = blk & 127;
    int d = dg * 8 + warp;
    int s0 = lane * 2;
    float A0 = -__expf(A_log[d * DS + s0]);
    float A1 = -__expf(A_log[d * DS + s0 + 1]);
    float Dd = Dp[d];
    float h0 = 0.f, h1 = 0.f;
    int m = b * LL;
    for (int t = 0; t < LL; t++, m++) {
        float dt_v = g_dt[m * DI + d];
        float u_v  = g_xconv[m * DI + d];
        float z_v  = g_xz[(size_t)m * (2 * DI) + DI + d];
        const float* row = g_xdbl + m * XDN;
        float2 Bv = *(const float2*)(row + DTR + s0);
        float2 Cv = *(const float2*)(row + DTR + DS + s0);
        float dA0 = __expf(dt_v * A0);
        float dA1 = __expf(dt_v * A1);
        float dtu = dt_v * u_v;
        h0 = fmaf(h0, dA0, dtu * Bv.x);
        h1 = fmaf(h1, dA1, dtu * Bv.y);
        float y = h0 * Cv.x + h1 * Cv.y;
#pragma unroll
        for (int off = 16; off; off >>= 1) y += __shfl_xor_sync(0xffffffffu, y, off);
        if (lane == 0)
            g_yss[m * DI + d] = (y + u_v * Dd) * siluf(z_v);
    }
}

// selu + permutation into fc1 layout: act[b, f*5000 + t*20 + p] = selu(out[b,t, p*24+f])
__global__ void selu_permute() {
    int o = blockIdx.x * blockDim.x + threadIdx.x;
    if (o >= NB * FLAT) return;
    int b = o / FLAT, r = o - b * FLAT;
    int f = r / 5000, tp = r - f * 5000;
    int t = tp / 20, p = tp - t * 20;
    int e = p * 24 + f;
    g_act[o] = seluf(g_outraw[(b * LL + t) * DM + e]);
}

// fc1: [8,120000] @ W[512,120000]^T, warp-per-output, K split over grid.y=8 (deterministic)
__global__ void fc1_kernel(const float* __restrict__ W) {
    const int KBLK = 15000, KC = 1000, NCH = 15;
    __shared__ float actS[8 * KC];   // 32 KB
    int warp = threadIdx.x >> 5, lane = threadIdx.x & 31;
    int n = blockIdx.x * 8 + warp;
    int kb0 = blockIdx.y * KBLK;
    float acc[8];
#pragma unroll
    for (int bb = 0; bb < 8; bb++) acc[bb] = 0.f;

    for (int c = 0; c < NCH; c++) {
        int kbase = kb0 + c * KC;
        __syncthreads();
        for (int i = threadIdx.x; i < 8 * KC; i += 256) {
            int bb = i / KC, kk = i - bb * KC;
            actS[i] = g_act[bb * FLAT + kbase + kk];
        }
        __syncthreads();
        const float* wrow = W + (size_t)n * FLAT + kbase;
        for (int kk = lane * 4; kk < KC; kk += 128) {
            float4 w4 = *(const float4*)(wrow + kk);
#pragma unroll
            for (int bb = 0; bb < 8; bb++) {
                float4 a4 = *(const float4*)&actS[bb * KC + kk];
                acc[bb] += w4.x * a4.x + w4.y * a4.y + w4.z * a4.z + w4.w * a4.w;
            }
        }
    }
#pragma unroll
    for (int bb = 0; bb < 8; bb++) {
        float v = acc[bb];
#pragma unroll
        for (int off = 16; off; off >>= 1) v += __shfl_xor_sync(0xffffffffu, v, off);
        if (lane == 0) g_y1p[blockIdx.y * (NB * 512) + bb * 512 + n] = v;
    }
}

__global__ void fc1_combine(const float* __restrict__ b1) {
    int i = blockIdx.x * blockDim.x + threadIdx.x;
    if (i >= NB * 512) return;
    int n = i & 511;
    float s = b1[n];
    for (int p = 0; p < 8; p++) s += g_y1p[p * (NB * 512) + i];
    g_y1[i] = s;
}

// small dense layers: warp per output element
__global__ void fc_small(const float* __restrict__ in, const float* __restrict__ W,
                         const float* __restrict__ bias, float* __restrict__ out,
                         int N, int K) {
    int gw = (blockIdx.x * blockDim.x + threadIdx.x) >> 5;
    int lane = threadIdx.x & 31;
    if (gw >= NB * N) return;
    int b = gw / N, n = gw - b * N;
    const float* ip = in + b * K;
    const float* wp = W + n * K;
    float s = 0.f;
    for (int k = lane; k < K; k += 32) s += ip[k] * wp[k];
#pragma unroll
    for (int off = 16; off; off >>= 1) s += __shfl_xor_sync(0xffffffffu, s, off);
    if (lane == 0) out[b * N + n] = s + bias[n];
}

// ---------------- launch ----------------
extern "C" void kernel_launch(void* const* d_in, const int* in_sizes, int n_in,
                              void* d_out, int out_size) {
    (void)in_sizes; (void)n_in; (void)out_size;
    const float* x          = (const float*)d_in[0];
    const float* in_proj_w  = (const float*)d_in[1];
    const float* conv_w     = (const float*)d_in[2];
    const float* conv_b     = (const float*)d_in[3];
    const float* x_proj_w   = (const float*)d_in[4];
    const float* dt_proj_w  = (const float*)d_in[5];
    const float* dt_proj_b  = (const float*)d_in[6];
    const float* A_log      = (const float*)d_in[7];
    const float* Dp         = (const float*)d_in[8];
    const float* out_proj_w = (const float*)d_in[9];
    const float* fc1_w      = (const float*)d_in[10];
    const float* fc1_b      = (const float*)d_in[11];
    const float* fc2_w      = (const float*)d_in[12];
    const float* fc2_b      = (const float*)d_in[13];
    const float* fc3_w      = (const float*)d_in[14];
    const float* fc3_b      = (const float*)d_in[15];
    const float* fc4_w      = (const float*)d_in[16];
    const float* fc4_b      = (const float*)d_in[17];

    float *p_u, *p_xz, *p_xconv, *p_xdblp, *p_xdbl, *p_outrawp, *p_outraw, *p_y1, *p_y2, *p_y3, *p_yss;
    cudaGetSymbolAddress((void**)&p_u, g_u);
    cudaGetSymbolAddress((void**)&p_xz, g_xz);
    cudaGetSymbolAddress((void**)&p_xconv, g_xconv);
    cudaGetSymbolAddress((void**)&p_xdblp, g_xdblp);
    cudaGetSymbolAddress((void**)&p_xdbl, g_xdbl);
    cudaGetSymbolAddress((void**)&p_outrawp, g_outrawp);
    cudaGetSymbolAddress((void**)&p_outraw, g_outraw);
    cudaGetSymbolAddress((void**)&p_yss, g_yss);
    cudaGetSymbolAddress((void**)&p_y1, g_y1);
    cudaGetSymbolAddress((void**)&p_y2, g_y2);
    cudaGetSymbolAddress((void**)&p_y3, g_y3);

    // 1) u
    pack_u<<<(MR * DM + 255) / 256, 256>>>(x);
    // 2) xz = u @ in_proj_w^T : [2000,2048]
    sgemm_nt<<<dim3(16, 16, 1), 256>>>(p_u, in_proj_w, p_xz, MR, 2 * DI, DM);
    // 3) conv + silu
    conv_silu<<<(MR * DI + 255) / 256, 256>>>(conv_w, conv_b);
    // 4) xdbl = xconv @ x_proj_w^T : [2000,160], split-K 8
    sgemm_nt<<<dim3(2, 16, 8), 256>>>(p_xconv, x_proj_w, p_xdblp, MR, XDN, DI);
    reduce_parts<<<(MR * XDN + 255) / 256, 256>>>(p_xdbl, p_xdblp, MR * XDN, 8);
    // 5) dt
    dt_softplus<<<dim3(125, 4), 256>>>(dt_proj_w, dt_proj_b);
    // 6) scan
    scan_kernel<<<1024, 256>>>(A_log, Dp);
    // 7) out = yss @ out_proj_w^T : [2000,512], split-K 4
    sgemm_nt<<<dim3(4, 16, 4), 256>>>(p_yss, out_proj_w, p_outrawp, MR, DM, DI);
    reduce_parts<<<(MR * DM + 255) / 256, 256>>>(p_outraw, p_outrawp, MR * DM, 4);
    // 8) selu + permute into fc1 layout
    selu_permute<<<(NB * FLAT + 255) / 256, 256>>>();
    // 9) fc1 (heavy, HBM-bound) with deterministic split-K
    fc1_kernel<<<dim3(64, 8), 256>>>(fc1_w);
    fc1_combine<<<(NB * 512 + 255) / 256, 256>>>(fc1_b);
    // 10) fc2..fc4
    fc_small<<<(NB * 256 * 32 + 127) / 128, 128>>>(p_y1, fc2_w, fc2_b, p_y2, 256, 512);
    fc_small<<<(NB * 64 * 32 + 127) / 128, 128>>>(p_y2, fc3_w, fc3_b, p_y3, 64, 256);
    fc_small<<<(NB * 8 * 32 + 127) / 128, 128>>>(p_y3, fc4_w, fc4_b, (float*)d_out, 8, 64);
}